// round 5
// baseline (speedup 1.0000x reference)
#include <cuda_runtime.h>

#define NN    100000   // nodes
#define RR    32       // relations
#define EE    3200000  // edges
#define EMBD  128      // embedding dim
#define HH    32       // hidden dim
#define BBASES 16      // num bases
#define CC    16       // output classes

#define SCAN_BLOCKS ((NN + 1023) / 1024)   // 98

typedef unsigned long long ull;

// -------- scratch (static device globals) --------
__device__ float g_deg[RR * NN];                 // 12.8 MB  edge-count per (rel, fr)
__device__ float g_h1[NN * HH];                  // 12.8 MB  hidden1 accumulator
__device__ float g_yb[NN * (BBASES * HH)];       // 204.8 MB yb[n][b*32+h] = emb @ bases1
__device__ float g_w2t[RR * CC * HH];            // 64 KB    w2 transposed to [r][c][h]
__device__ int   g_cnt[NN];                      // histogram of `to`
__device__ int   g_off[NN + 1];                  // group offsets (exclusive scan)
__device__ int   g_pos[NN];                      // running scatter positions
__device__ int   g_bsum[SCAN_BLOCKS];            // per-block scan totals
__device__ int2  g_ev[EE];                       // sorted edges: {(r<<17)|f, bits(val)}

// -------- init --------
__global__ void k_init(const float* __restrict__ bias2, float* __restrict__ out) {
    int i = blockIdx.x * blockDim.x + threadIdx.x;
    int stride = gridDim.x * blockDim.x;
    for (int idx = i; idx < RR * NN; idx += stride) g_deg[idx] = 0.f;
    for (int idx = i; idx < NN * HH; idx += stride) g_h1[idx] = 0.f;
    for (int idx = i; idx < NN; idx += stride) g_cnt[idx] = 0;
    for (int idx = i; idx < NN * CC; idx += stride) out[idx] = bias2[idx & (CC - 1)];
}

// -------- w2t[r][c][h] = sum_b comps2[r,b] * bases2[b,h,c] --------
__global__ void k_w2t(const float* __restrict__ comps2, const float* __restrict__ bases2) {
    int idx = blockIdx.x * blockDim.x + threadIdx.x;
    if (idx >= RR * CC * HH) return;
    int r = idx >> 9;
    int c = (idx >> 5) & (CC - 1);
    int h = idx & (HH - 1);
    float acc = 0.f;
    #pragma unroll
    for (int b = 0; b < BBASES; b++)
        acc += comps2[r * BBASES + b] * bases2[(b * HH + h) * CC + c];
    g_w2t[idx] = acc;
}

// -------- deg + to-histogram --------
__global__ void k_deg(const int* __restrict__ rel, const int* __restrict__ fr,
                      const int* __restrict__ to) {
    int i = blockIdx.x * blockDim.x + threadIdx.x;
    int stride = gridDim.x * blockDim.x;
    for (int e = i; e < EE; e += stride) {
        atomicAdd(&g_deg[rel[e] * NN + fr[e]], 1.0f);
        atomicAdd(&g_cnt[to[e]], 1);
    }
}

// -------- multi-block exclusive scan --------
__global__ void k_scan1() {
    __shared__ int s[1024];
    int tid = threadIdx.x;
    int i = blockIdx.x * 1024 + tid;
    int v = (i < NN) ? g_cnt[i] : 0;
    s[tid] = v;
    __syncthreads();
    #pragma unroll
    for (int d = 1; d < 1024; d <<= 1) {
        int t = (tid >= d) ? s[tid - d] : 0;
        __syncthreads();
        s[tid] += t;
        __syncthreads();
    }
    if (i < NN) g_off[i] = s[tid] - v;
    if (tid == 1023) g_bsum[blockIdx.x] = s[1023];
}

__global__ void k_scan2() {
    __shared__ int s[128];
    int tid = threadIdx.x;
    int v = (tid < SCAN_BLOCKS) ? g_bsum[tid] : 0;
    s[tid] = v;
    __syncthreads();
    #pragma unroll
    for (int d = 1; d < 128; d <<= 1) {
        int t = (tid >= d) ? s[tid - d] : 0;
        __syncthreads();
        s[tid] += t;
        __syncthreads();
    }
    if (tid < SCAN_BLOCKS) g_bsum[tid] = s[tid] - v;
}

__global__ void k_scan3() {
    int i = blockIdx.x * 1024 + threadIdx.x;
    if (i < NN) {
        int o = g_off[i] + g_bsum[i >> 10];
        g_off[i] = o;
        g_pos[i] = o;
    }
    if (i == 0) g_off[NN] = EE;
}

// -------- scatter: to-sorted edge records with precomputed val --------
__global__ void k_scatter(const int* __restrict__ rel, const int* __restrict__ fr,
                          const int* __restrict__ to) {
    int i = blockIdx.x * blockDim.x + threadIdx.x;
    int stride = gridDim.x * blockDim.x;
    for (int e = i; e < EE; e += stride) {
        int r = rel[e], f = fr[e];
        int pos = atomicAdd(&g_pos[to[e]], 1);
        float val = 1.0f / g_deg[r * NN + f];
        g_ev[pos] = make_int2((r << 17) | f, __float_as_int(val));
    }
}

// -------- packed f32x2 FMA (FFMA2 in SASS; only reachable via PTX) --------
__device__ __forceinline__ ull fma2(ull a, ull b, ull c) {
    ull d;
    asm("fma.rn.f32x2 %0, %1, %2, %3;" : "=l"(d) : "l"(a), "l"(b), "l"(c));
    return d;
}

// -------- GEMM: yb = emb @ W, 128x128x16 tile, 8x8/thread, packed f32x2 --------
#define GBM 128
#define GBN 128
#define GBK 16
__global__ void __launch_bounds__(256) k_gemm1(const float* __restrict__ A,
                                               const float* __restrict__ bases1) {
    __shared__ float Asd[GBK][2 * GBM];   // 16KB: A transposed + duplicated per value
    __shared__ float Bs[GBK][GBN];        // 8KB
    int tid = threadIdx.x;
    int tx = tid & 15;                    // n-group: cols [tx*8, tx*8+8)
    int ty = tid >> 4;                    // m-group: rows [ty*8, ty*8+8)
    int m0 = blockIdx.y * GBM;
    int n0 = blockIdx.x * GBN;

    // A load: thread -> row arow (0..127), k-cols acol..acol+7 (two float4)
    int arow = tid >> 1;
    int acol = (tid & 1) << 3;
    // B load: thread -> k-row brow (0..15), j-cols bcol..bcol+7
    int brow = tid >> 4;
    int bcol = (tid & 15) << 3;
    int j = n0 + bcol;
    const float* bsrc = bases1 + (j >> 5) * (EMBD * HH) + (j & 31);

    ull acc[8][4];
    #pragma unroll
    for (int i = 0; i < 8; i++)
        #pragma unroll
        for (int p = 0; p < 4; p++) acc[i][p] = 0ull;

    int m_a = m0 + arow;
    for (int k0 = 0; k0 < EMBD; k0 += GBK) {
        float4 a0 = make_float4(0.f, 0.f, 0.f, 0.f);
        float4 a1 = make_float4(0.f, 0.f, 0.f, 0.f);
        if (m_a < NN) {
            a0 = *(const float4*)(A + m_a * EMBD + k0 + acol);
            a1 = *(const float4*)(A + m_a * EMBD + k0 + acol + 4);
        }
        *(float2*)&Asd[acol + 0][2 * arow] = make_float2(a0.x, a0.x);
        *(float2*)&Asd[acol + 1][2 * arow] = make_float2(a0.y, a0.y);
        *(float2*)&Asd[acol + 2][2 * arow] = make_float2(a0.z, a0.z);
        *(float2*)&Asd[acol + 3][2 * arow] = make_float2(a0.w, a0.w);
        *(float2*)&Asd[acol + 4][2 * arow] = make_float2(a1.x, a1.x);
        *(float2*)&Asd[acol + 5][2 * arow] = make_float2(a1.y, a1.y);
        *(float2*)&Asd[acol + 6][2 * arow] = make_float2(a1.z, a1.z);
        *(float2*)&Asd[acol + 7][2 * arow] = make_float2(a1.w, a1.w);
        *(float4*)&Bs[brow][bcol]     = *(const float4*)(bsrc + (k0 + brow) * HH);
        *(float4*)&Bs[brow][bcol + 4] = *(const float4*)(bsrc + (k0 + brow) * HH + 4);
        __syncthreads();
        #pragma unroll
        for (int kk = 0; kk < GBK; kk++) {
            ull bp[4];
            *(float4*)&bp[0] = *(const float4*)&Bs[kk][tx * 8];      // pairs 0,1
            *(float4*)&bp[2] = *(const float4*)&Bs[kk][tx * 8 + 4];  // pairs 2,3
            #pragma unroll
            for (int i = 0; i < 8; i++) {
                ull ap = *(const ull*)&Asd[kk][2 * (ty * 8 + i)];
                acc[i][0] = fma2(ap, bp[0], acc[i][0]);
                acc[i][1] = fma2(ap, bp[1], acc[i][1]);
                acc[i][2] = fma2(ap, bp[2], acc[i][2]);
                acc[i][3] = fma2(ap, bp[3], acc[i][3]);
            }
        }
        __syncthreads();
    }
    #pragma unroll
    for (int i = 0; i < 8; i++) {
        int m = m0 + ty * 8 + i;
        if (m < NN) {
            float* dst = &g_yb[m * 512 + n0 + tx * 8];
            float4 v0, v1;
            *(ull*)&v0.x = acc[i][0]; *(ull*)&v0.z = acc[i][1];
            *(ull*)&v1.x = acc[i][2]; *(ull*)&v1.z = acc[i][3];
            *(float4*)dst       = v0;
            *(float4*)(dst + 4) = v1;
        }
    }
}

__device__ __forceinline__ void red_add_v4(float* addr, float a, float b, float c, float d) {
    asm volatile("red.global.add.v4.f32 [%0], {%1, %2, %3, %4};"
                 :: "l"(addr), "f"(a), "f"(b), "f"(c), "f"(d) : "memory");
}

// -------- pass1 (sorted by to): block per node n; 4 edges/warp, lane = 4 h's --------
__global__ void k_pass1s(const float* __restrict__ comps1) {
    __shared__ float syb[BBASES * HH];   // 512: yb row of node n
    __shared__ float sc1[RR * BBASES];   // 512: comps1
    int n = blockIdx.x;
    int tid = threadIdx.x;               // 128 threads
    *(float4*)&syb[tid << 2] = *(const float4*)&g_yb[n * 512 + (tid << 2)];
    *(float4*)&sc1[tid << 2] = *(const float4*)&comps1[tid << 2];
    __syncthreads();
    int start = g_off[n], end = g_off[n + 1];
    int lane = tid & 31;
    int w = tid >> 5;
    int sub = lane >> 3;                 // 0..3: which edge in the quad
    int h4 = (lane & 7) << 2;            // h base: 0,4,...,28
    for (int base = start + (w << 2); base < end; base += 16) {
        int e = base + sub;
        if (e < end) {
            int2 ev = g_ev[e];
            int r = ev.x >> 17;
            int f = ev.x & 0x1FFFF;
            float val = __int_as_float(ev.y);
            float a0 = 0.f, a1 = 0.f, a2 = 0.f, a3 = 0.f;
            #pragma unroll
            for (int b = 0; b < BBASES; b++) {
                float c = sc1[r * BBASES + b];
                float4 y = *(const float4*)&syb[b * HH + h4];
                a0 += c * y.x; a1 += c * y.y; a2 += c * y.z; a3 += c * y.w;
            }
            red_add_v4(&g_h1[f * HH + h4], val * a0, val * a1, val * a2, val * a3);
        }
    }
}

// -------- pass2 (sorted by to): block per node; relu fused; 8 edges/warp, lane = 4 c's
__global__ void k_pass2s(const float* __restrict__ bias1, float* __restrict__ out) {
    __shared__ float sh1[HH];
    int n = blockIdx.x;
    int tid = threadIdx.x;               // 128 threads
    if (tid < HH) sh1[tid] = fmaxf(g_h1[n * HH + tid] + bias1[tid], 0.f);
    __syncthreads();
    float4 hv[8];
    #pragma unroll
    for (int q = 0; q < 8; q++) hv[q] = *(const float4*)&sh1[q << 2];

    int start = g_off[n], end = g_off[n + 1];
    int lane = tid & 31;
    int w = tid >> 5;
    int sub = lane >> 2;                 // 0..7: which edge in the octet
    int c0 = (lane & 3) << 2;            // c base: 0,4,8,12
    for (int base = start + (w << 3); base < end; base += 32) {
        int e = base + sub;
        if (e < end) {
            int2 ev = g_ev[e];
            int r = ev.x >> 17;
            int f = ev.x & 0x1FFFF;
            float val = __int_as_float(ev.y);
            const float4* w2 = (const float4*)&g_w2t[(r * CC + c0) * HH];
            float acc[4];
            #pragma unroll
            for (int c = 0; c < 4; c++) {
                float s = 0.f;
                #pragma unroll
                for (int q = 0; q < 8; q++) {
                    float4 b = w2[c * 8 + q];
                    float4 a = hv[q];
                    s += a.x * b.x + a.y * b.y + a.z * b.z + a.w * b.w;
                }
                acc[c] = s * val;
            }
            red_add_v4(&out[f * CC + c0], acc[0], acc[1], acc[2], acc[3]);
        }
    }
}

extern "C" void kernel_launch(void* const* d_in, const int* in_sizes, int n_in,
                              void* d_out, int out_size) {
    const float* emb    = (const float*)d_in[0];
    const float* comps1 = (const float*)d_in[1];
    const float* bases1 = (const float*)d_in[2];
    const float* comps2 = (const float*)d_in[3];
    const float* bases2 = (const float*)d_in[4];
    const float* bias1  = (const float*)d_in[5];
    const float* bias2  = (const float*)d_in[6];
    const int*   rel    = (const int*)d_in[7];
    const int*   fr     = (const int*)d_in[8];
    const int*   to     = (const int*)d_in[9];
    float* out = (float*)d_out;

    k_init<<<12500, 256>>>(bias2, out);
    k_w2t<<<(RR * CC * HH + 255) / 256, 256>>>(comps2, bases2);
    k_deg<<<4096, 256>>>(rel, fr, to);
    k_scan1<<<SCAN_BLOCKS, 1024>>>();
    k_scan2<<<1, 128>>>();
    k_scan3<<<SCAN_BLOCKS, 1024>>>();
    k_scatter<<<4096, 256>>>(rel, fr, to);
    k_gemm1<<<dim3((BBASES * HH) / GBN, (NN + GBM - 1) / GBM), 256>>>(emb, bases1);
    k_pass1s<<<NN, 128>>>(comps1);
    k_pass2s<<<NN, 128>>>(bias1, out);
}

// round 6
// speedup vs baseline: 2.5198x; 2.5198x over previous
#include <cuda_runtime.h>

#define NN    100000   // nodes
#define RR    32       // relations
#define EE    3200000  // edges
#define EMBD  128      // embedding dim
#define HH    32       // hidden dim
#define BBASES 16      // num bases
#define CC    16       // output classes

#define SCAN_BLOCKS ((NN + 1023) / 1024)   // 98

// -------- scratch (static device globals) --------
__device__ float g_deg[RR * NN];                 // 12.8 MB  edge-count per (rel, fr)
__device__ float g_h1[NN * HH];                  // 12.8 MB  hidden1 accumulator
__device__ float g_yb[NN * (BBASES * HH)];       // 204.8 MB yb[n][b*32+h] = emb @ bases1
__device__ int   g_cnt[NN];                      // histogram of `to`
__device__ int   g_off[NN + 1];                  // group offsets (exclusive scan)
__device__ int   g_pos[NN];                      // running scatter positions
__device__ int   g_bsum[SCAN_BLOCKS];            // per-block scan totals
__device__ int2  g_ev[EE];                       // sorted edges: {(r<<17)|f, bits(val)}

// -------- init --------
__global__ void k_init(const float* __restrict__ bias2, float* __restrict__ out) {
    int i = blockIdx.x * blockDim.x + threadIdx.x;
    int stride = gridDim.x * blockDim.x;
    for (int idx = i; idx < RR * NN; idx += stride) g_deg[idx] = 0.f;
    for (int idx = i; idx < NN * HH; idx += stride) g_h1[idx] = 0.f;
    for (int idx = i; idx < NN; idx += stride) g_cnt[idx] = 0;
    for (int idx = i; idx < NN * CC; idx += stride) out[idx] = bias2[idx & (CC - 1)];
}

// -------- deg + to-histogram --------
__global__ void k_deg(const int* __restrict__ rel, const int* __restrict__ fr,
                      const int* __restrict__ to) {
    int i = blockIdx.x * blockDim.x + threadIdx.x;
    int stride = gridDim.x * blockDim.x;
    for (int e = i; e < EE; e += stride) {
        atomicAdd(&g_deg[rel[e] * NN + fr[e]], 1.0f);
        atomicAdd(&g_cnt[to[e]], 1);
    }
}

// -------- multi-block exclusive scan --------
__global__ void k_scan1() {
    __shared__ int s[1024];
    int tid = threadIdx.x;
    int i = blockIdx.x * 1024 + tid;
    int v = (i < NN) ? g_cnt[i] : 0;
    s[tid] = v;
    __syncthreads();
    #pragma unroll
    for (int d = 1; d < 1024; d <<= 1) {
        int t = (tid >= d) ? s[tid - d] : 0;
        __syncthreads();
        s[tid] += t;
        __syncthreads();
    }
    if (i < NN) g_off[i] = s[tid] - v;
    if (tid == 1023) g_bsum[blockIdx.x] = s[1023];
}

__global__ void k_scan2() {
    __shared__ int s[128];
    int tid = threadIdx.x;
    int v = (tid < SCAN_BLOCKS) ? g_bsum[tid] : 0;
    s[tid] = v;
    __syncthreads();
    #pragma unroll
    for (int d = 1; d < 128; d <<= 1) {
        int t = (tid >= d) ? s[tid - d] : 0;
        __syncthreads();
        s[tid] += t;
        __syncthreads();
    }
    if (tid < SCAN_BLOCKS) g_bsum[tid] = s[tid] - v;
}

__global__ void k_scan3() {
    int i = blockIdx.x * 1024 + threadIdx.x;
    if (i < NN) {
        int o = g_off[i] + g_bsum[i >> 10];
        g_off[i] = o;
        g_pos[i] = o;
    }
    if (i == 0) g_off[NN] = EE;
}

// -------- scatter: to-sorted edge records with precomputed val --------
__global__ void k_scatter(const int* __restrict__ rel, const int* __restrict__ fr,
                          const int* __restrict__ to) {
    int i = blockIdx.x * blockDim.x + threadIdx.x;
    int stride = gridDim.x * blockDim.x;
    for (int e = i; e < EE; e += stride) {
        int r = rel[e], f = fr[e];
        int pos = atomicAdd(&g_pos[to[e]], 1);
        float val = 1.0f / g_deg[r * NN + f];
        g_ev[pos] = make_int2((r << 17) | f, __float_as_int(val));
    }
}

// -------- GEMM (round-3 scalar, at FFMA roofline): yb = emb @ W ----------------
#define BM 64
#define BN 64
#define BK 16
__global__ void k_gemm1(const float* __restrict__ A, const float* __restrict__ bases1) {
    __shared__ float As[BK][BM];
    __shared__ float Bs[BK][BN];
    int m0 = blockIdx.y * BM;
    int n0 = blockIdx.x * BN;
    int tid = threadIdx.x;
    int tx = tid & 15;
    int ty = tid >> 4;
    int arow = tid >> 2;
    int acol = (tid & 3) << 2;
    int brow = tid >> 4;
    int bcol = (tid & 15) << 2;
    int j  = n0 + bcol;
    int bb = j >> 5;
    int hh = j & 31;
    const float* bsrc = bases1 + bb * (EMBD * HH) + hh;

    float acc[4][4] = {};
    for (int k0 = 0; k0 < EMBD; k0 += BK) {
        float4 av = make_float4(0.f, 0.f, 0.f, 0.f);
        int m = m0 + arow;
        if (m < NN) av = *(const float4*)(A + m * EMBD + k0 + acol);
        As[acol + 0][arow] = av.x;
        As[acol + 1][arow] = av.y;
        As[acol + 2][arow] = av.z;
        As[acol + 3][arow] = av.w;
        float4 bv = *(const float4*)(bsrc + (k0 + brow) * HH);
        *(float4*)&Bs[brow][bcol] = bv;
        __syncthreads();
        #pragma unroll
        for (int kk = 0; kk < BK; kk++) {
            float4 a = *(const float4*)&As[kk][ty << 2];
            float4 b = *(const float4*)&Bs[kk][tx << 2];
            acc[0][0] += a.x * b.x; acc[0][1] += a.x * b.y; acc[0][2] += a.x * b.z; acc[0][3] += a.x * b.w;
            acc[1][0] += a.y * b.x; acc[1][1] += a.y * b.y; acc[1][2] += a.y * b.z; acc[1][3] += a.y * b.w;
            acc[2][0] += a.z * b.x; acc[2][1] += a.z * b.y; acc[2][2] += a.z * b.z; acc[2][3] += a.z * b.w;
            acc[3][0] += a.w * b.x; acc[3][1] += a.w * b.y; acc[3][2] += a.w * b.z; acc[3][3] += a.w * b.w;
        }
        __syncthreads();
    }
    #pragma unroll
    for (int i = 0; i < 4; i++) {
        int m = m0 + (ty << 2) + i;
        if (m < NN)
            *(float4*)&g_yb[m * (BBASES * HH) + n0 + (tx << 2)] =
                make_float4(acc[i][0], acc[i][1], acc[i][2], acc[i][3]);
    }
}

__device__ __forceinline__ void red_add_v4(float* addr, float a, float b, float c, float d) {
    asm volatile("red.global.add.v4.f32 [%0], {%1, %2, %3, %4};"
                 :: "l"(addr), "f"(a), "f"(b), "f"(c), "f"(d) : "memory");
}

// -------- pass1 persistent: per node compute sxw[r,h] for all r, then cheap edges --
#define P1_GRID 1184
__global__ void __launch_bounds__(128) k_pass1p(const float* __restrict__ comps1) {
    __shared__ float sc1[RR * BBASES];    // 512
    __shared__ float syb[BBASES * HH];    // 512
    __shared__ float sxw[RR * HH];        // 1024
    int tid = threadIdx.x;
    *(float4*)&sc1[tid << 2] = *(const float4*)&comps1[tid << 2];
    __syncthreads();

    int lane = tid & 31;
    int w = tid >> 5;
    int sub = lane >> 3;                  // 0..3
    int h4 = (lane & 7) << 2;             // 0,4,...,28
    int r_c = tid >> 2;                   // sxw compute: relation 0..31
    int h0 = (tid & 3) << 3;              // 8 h's per thread

    for (int n = blockIdx.x; n < NN; n += gridDim.x) {
        *(float4*)&syb[tid << 2] = *(const float4*)&g_yb[n * 512 + (tid << 2)];
        __syncthreads();
        float acc[8] = {};
        #pragma unroll
        for (int b = 0; b < BBASES; b++) {
            float c = sc1[r_c * BBASES + b];
            #pragma unroll
            for (int j = 0; j < 8; j++)
                acc[j] += c * syb[b * HH + h0 + j];
        }
        #pragma unroll
        for (int j = 0; j < 8; j++) sxw[r_c * HH + h0 + j] = acc[j];
        __syncthreads();

        int start = g_off[n], end = g_off[n + 1];
        for (int base = start + (w << 2); base < end; base += 16) {
            int e = base + sub;
            if (e < end) {
                int2 ev = g_ev[e];
                int r = ev.x >> 17;
                int f = ev.x & 0x1FFFF;
                float val = __int_as_float(ev.y);
                float4 x = *(const float4*)&sxw[r * HH + h4];
                red_add_v4(&g_h1[f * HH + h4], val * x.x, val * x.y, val * x.z, val * x.w);
            }
        }
        __syncthreads();
    }
}

// -------- pass2 persistent: bases2/comps2 staged once; per node t=h1@bases2, q=comps2@t
#define P2_GRID 888
#define SB2_STRIDE 528                      // 512 + 16 pad (bank-conflict-free halves)
__global__ void __launch_bounds__(128) k_pass2p(const float* __restrict__ comps2,
                                                const float* __restrict__ bases2,
                                                const float* __restrict__ bias1,
                                                float* __restrict__ out) {
    __shared__ float sb2[BBASES * SB2_STRIDE]; // 33KB: bases2[b][h*16+c] padded
    __shared__ float sc2[RR * BBASES];         // 512
    __shared__ float sbias[HH];
    __shared__ float sh1[HH];
    __shared__ float st[BBASES * CC];          // 256: t[b][c]
    __shared__ float sq[RR * CC];              // 512: q[r][c]
    int tid = threadIdx.x;
    for (int i = tid; i < BBASES * HH * CC / 4; i += 128) {
        int b = (i << 2) >> 9;                 // /512
        int o = (i << 2) & 511;
        *(float4*)&sb2[b * SB2_STRIDE + o] = *(const float4*)&bases2[b * 512 + o];
    }
    *(float4*)&sc2[tid << 2] = *(const float4*)&comps2[tid << 2];
    if (tid < HH) sbias[tid] = bias1[tid];
    __syncthreads();

    int lane = tid & 31;
    int w = tid >> 5;
    int sub = lane >> 2;                  // 0..7
    int c0 = (lane & 3) << 2;             // 0,4,8,12

    for (int n = blockIdx.x; n < NN; n += gridDim.x) {
        if (tid < HH) sh1[tid] = fmaxf(g_h1[n * HH + tid] + sbias[tid], 0.f);
        __syncthreads();
        // t[b][c] = sum_h sh1[h] * bases2[b][h][c]   (256 vals, 2 per thread)
        {
            int i = tid;            // first val
            int b = i >> 4, c = i & 15;
            float a0 = 0.f, a1 = 0.f;
            int b2 = (i + 128) >> 4, c2 = (i + 128) & 15;
            #pragma unroll
            for (int h = 0; h < HH; h++) {
                float hv = sh1[h];
                a0 += hv * sb2[b * SB2_STRIDE + h * CC + c];
                a1 += hv * sb2[b2 * SB2_STRIDE + h * CC + c2];
            }
            st[i] = a0;
            st[i + 128] = a1;
        }
        __syncthreads();
        // q[r][c] = sum_b comps2[r][b] * t[b][c]   (512 vals, 4 per thread)
        #pragma unroll
        for (int k = 0; k < 4; k++) {
            int i = tid + k * 128;
            int r = i >> 4, c = i & 15;
            float a = 0.f;
            #pragma unroll
            for (int b = 0; b < BBASES; b++)
                a += sc2[r * BBASES + b] * st[b * CC + c];
            sq[i] = a;
        }
        __syncthreads();

        int start = g_off[n], end = g_off[n + 1];
        for (int base = start + (w << 3); base < end; base += 32) {
            int e = base + sub;
            if (e < end) {
                int2 ev = g_ev[e];
                int r = ev.x >> 17;
                int f = ev.x & 0x1FFFF;
                float val = __int_as_float(ev.y);
                float4 q = *(const float4*)&sq[r * CC + c0];
                red_add_v4(&out[f * CC + c0], val * q.x, val * q.y, val * q.z, val * q.w);
            }
        }
        __syncthreads();
    }
}

extern "C" void kernel_launch(void* const* d_in, const int* in_sizes, int n_in,
                              void* d_out, int out_size) {
    const float* emb    = (const float*)d_in[0];
    const float* comps1 = (const float*)d_in[1];
    const float* bases1 = (const float*)d_in[2];
    const float* comps2 = (const float*)d_in[3];
    const float* bases2 = (const float*)d_in[4];
    const float* bias1  = (const float*)d_in[5];
    const float* bias2  = (const float*)d_in[6];
    const int*   rel    = (const int*)d_in[7];
    const int*   fr     = (const int*)d_in[8];
    const int*   to     = (const int*)d_in[9];
    float* out = (float*)d_out;

    k_init<<<12500, 256>>>(bias2, out);
    k_deg<<<4096, 256>>>(rel, fr, to);
    k_scan1<<<SCAN_BLOCKS, 1024>>>();
    k_gemm1<<<dim3((BBASES * HH) / BN, (NN + BM - 1) / BM), 256>>>(emb, bases1);  // 4th: profiled
    k_scan2<<<1, 128>>>();
    k_scan3<<<SCAN_BLOCKS, 1024>>>();
    k_scatter<<<4096, 256>>>(rel, fr, to);
    k_pass1p<<<P1_GRID, 128>>>(comps1);
    k_pass2p<<<P2_GRID, 128>>>(comps2, bases2, bias1, out);
}